// round 14
// baseline (speedup 1.0000x reference)
#include <cuda_runtime.h>
#include <cuda_bf16.h>
#include <mma.h>
#include <cstdint>

using namespace nvcuda;

#define Bb 8
#define Cc 512
#define Nn 256
#define Tt 32
#define Pp 2048   // B*N
#define Mm 2048   // 4*C
#define Kk 512    // C

#define BM 128
#define BN 128
#define BK 32
#define NKIT (Kk / BK)   // 16
#define LDA 40           // 32 + 8 pad (bf16)
#define LDB 136          // 128 + 8 pad
#define LDZ 132          // fp32 staging pitch

#define SZ_A (BM * LDA)              // 5120 bf16
#define SZ_B (BK * LDB)              // 4352 bf16
#define BUF_ELEMS (2 * SZ_A + 2 * SZ_B)   // 18944 bf16 per stage
#define SMEM_XP (3 * BUF_ELEMS * 2)       // 113664 B (3-stage)

// ---- persistent step kernel tiling: 256x128 block, 8 warps (4x2), 64x64 warp tiles ----
#define BM2 256
#define SZ_A2 (BM2 * LDA)                   // 10240 bf16
#define SZ_B2 (BK * LDB)                    // 4352 bf16
#define BUF2 (2 * SZ_A2 + 2 * SZ_B2)        // 29184 bf16 per stage
#define SMEM_ST (3 * BUF2 * 2 + 1024)       // 176128 B (3 stages + bias)
#define NBLK_ST 128                          // 8 m-tiles x 16 p-tiles; 1 CTA/SM

// ------------ device scratch (no allocs allowed) ------------
__device__ __align__(16) __nv_bfloat16 g_XtH[(size_t)Tt * Kk * Pp]; // [t][k][p]
__device__ __align__(16) __nv_bfloat16 g_XtL[(size_t)Tt * Kk * Pp];
__device__ __align__(16) float         g_XP[(size_t)Tt * Mm * Pp];  // [t][m][p], m=4c+g
__device__ __align__(16) float         g_Hseq[(size_t)Tt * Cc * Pp];// [t][c][p]
__device__ __align__(16) __nv_bfloat16 g_WxH[Mm * Kk], g_WxL[Mm * Kk]; // rows m=4c+g
__device__ __align__(16) __nv_bfloat16 g_WhH[Mm * Kk], g_WhL[Mm * Kk];
__device__ __align__(16) __nv_bfloat16 g_HH[2][Kk * Pp], g_HL[2][Kk * Pp]; // H: [k][p]
__device__ __align__(16) float         g_Cell[Cc * Pp];
__device__ __align__(16) float         g_bias[Mm];                  // bx+bh, index g*C+c
__device__ unsigned g_barrier_cnt;

// ------------ cp.async helpers ------------
__device__ __forceinline__ void cp16(void* dst, const void* src) {
    unsigned int d = (unsigned int)__cvta_generic_to_shared(dst);
    asm volatile("cp.async.cg.shared.global [%0], [%1], 16;\n" :: "r"(d), "l"(src));
}
#define CP_COMMIT() asm volatile("cp.async.commit_group;\n" ::)
#define CP_WAIT1()  asm volatile("cp.async.wait_group 1;\n" ::)
#define CP_WAIT0()  asm volatile("cp.async.wait_group 0;\n" ::)

__device__ __forceinline__ void bf16_split(float v, __nv_bfloat16& h, __nv_bfloat16& l) {
    h = __float2bfloat16(v);
    l = __float2bfloat16(v - __bfloat162float(h));
}

// monotonic grid barrier (all NBLK_ST CTAs resident: 128 CTAs, 1/SM)
__device__ __forceinline__ void grid_barrier(unsigned target) {
    __syncthreads();
    if (threadIdx.x == 0) {
        __threadfence();
        atomicAdd(&g_barrier_cnt, 1u);
        volatile unsigned* p = &g_barrier_cnt;
        while (*p < target) { }
        __threadfence();
    }
    __syncthreads();
}

// ------------ setup kernels ------------
__global__ void init_state() {
    int i = blockIdx.x * blockDim.x + threadIdx.x;
    if (i == 0) g_barrier_cnt = 0;             // reset each graph replay
    if (i < Kk * Pp) {
        __nv_bfloat16 z = __float2bfloat16(0.f);
        g_HH[0][i] = z; g_HH[1][i] = z;
        g_HL[0][i] = z; g_HL[1][i] = z;
        g_Cell[i] = 0.f;
    }
}

__global__ void split_weights(const float* __restrict__ Wx, const float* __restrict__ Wh,
                              const float* __restrict__ bx, const float* __restrict__ bh) {
    int idx = blockIdx.x * blockDim.x + threadIdx.x;
    if (idx >= 4 * Cc * Cc) return;
    int g = idx >> 18;
    int rem = idx & ((1 << 18) - 1);
    int c = rem >> 9;
    int k = rem & 511;
    int m = (c << 2) | g;
    __nv_bfloat16 h, l;
    bf16_split(Wx[idx], h, l);
    g_WxH[m * Kk + k] = h; g_WxL[m * Kk + k] = l;
    bf16_split(Wh[idx], h, l);
    g_WhH[m * Kk + k] = h; g_WhL[m * Kk + k] = l;
    if (idx < 4 * Cc) g_bias[idx] = bx[idx] + bh[idx];   // index g*C+c
}

// x (B,C,N,T) -> Xt hi/lo [t][c][b*N+n]
__global__ void transpose_split_x(const float* __restrict__ x) {
    __shared__ float tile[32][33];
    int bid   = blockIdx.x;
    int ntile = bid & 7;
    int bc    = bid >> 3;
    int c     = bc & (Cc - 1);
    int b     = bc >> 9;
    int tid = threadIdx.x;
    int tr = tid >> 5, tc = tid & 31;
    const float* src = x + ((size_t)(b * Cc + c) * Nn + ntile * 32) * Tt;
#pragma unroll
    for (int r0 = 0; r0 < 32; r0 += 8)
        tile[r0 + tr][tc] = src[(size_t)(r0 + tr) * Tt + tc];
    __syncthreads();
#pragma unroll
    for (int r0 = 0; r0 < 32; r0 += 8) {
        int t = r0 + tr;
        float v = tile[tc][t];
        __nv_bfloat16 h, l;
        bf16_split(v, h, l);
        size_t o = ((size_t)t * Kk + c) * Pp + b * Nn + ntile * 32 + tc;
        g_XtH[o] = h; g_XtL[o] = l;
    }
}

// g_Hseq[t][c][b*N+n] -> out (B,C,N,T)
__global__ void transpose_out(float* __restrict__ out) {
    __shared__ float tile[32][33];
    int bid   = blockIdx.x;
    int ntile = bid & 7;
    int bc    = bid >> 3;
    int c     = bc & (Cc - 1);
    int b     = bc >> 9;
    int tid = threadIdx.x;
    int tr = tid >> 5, tc = tid & 31;
#pragma unroll
    for (int r0 = 0; r0 < 32; r0 += 8) {
        int t = r0 + tr;
        tile[tc][t] = g_Hseq[((size_t)t * Cc + c) * Pp + b * Nn + ntile * 32 + tc];
    }
    __syncthreads();
    float* dst = out + ((size_t)(b * Cc + c) * Nn + ntile * 32) * Tt;
#pragma unroll
    for (int r0 = 0; r0 < 32; r0 += 8) {
        int n = r0 + tr;
        dst[(size_t)n * Tt + tc] = tile[n][tc];
    }
}

// =========== CORE A: 128 thr, 2x2 warps, 64x64 tiles, 3-stage (for xp_gemm) ===========
struct AccXP {
    wmma::fragment<wmma::accumulator, 16, 16, 16, float> a[4][4];
};

__device__ __forceinline__ void gemm_core_xp(
    const __nv_bfloat16* __restrict__ AH, const __nv_bfloat16* __restrict__ AL,
    const __nv_bfloat16* __restrict__ BH, const __nv_bfloat16* __restrict__ BL,
    __nv_bfloat16* sm, int tid, int wm, int wn, AccXP& acc)
{
#pragma unroll
    for (int i = 0; i < 4; i++)
#pragma unroll
        for (int j = 0; j < 4; j++) wmma::fill_fragment(acc.a[i][j], 0.f);

    auto load_tiles = [&](int buf, int k0) {
        __nv_bfloat16* base = sm + buf * BUF_ELEMS;
        __nv_bfloat16* asH = base;
        __nv_bfloat16* asL = base + SZ_A;
        __nv_bfloat16* bsH = base + 2 * SZ_A;
        __nv_bfloat16* bsL = base + 2 * SZ_A + SZ_B;
#pragma unroll
        for (int it = 0; it < 4; ++it) {
            int idx = tid + it * 128;
            int row = idx >> 2, q = idx & 3;
            cp16(asH + row * LDA + q * 8, AH + (size_t)row * Kk + k0 + q * 8);
            cp16(asL + row * LDA + q * 8, AL + (size_t)row * Kk + k0 + q * 8);
        }
#pragma unroll
        for (int it = 0; it < 4; ++it) {
            int idx = tid + it * 128;
            int kk = idx >> 4, q = idx & 15;
            cp16(bsH + kk * LDB + q * 8, BH + (size_t)(k0 + kk) * Pp + q * 8);
            cp16(bsL + kk * LDB + q * 8, BL + (size_t)(k0 + kk) * Pp + q * 8);
        }
        CP_COMMIT();
    };

    auto compute = [&](int buf) {
        __nv_bfloat16* base = sm + buf * BUF_ELEMS;
        __nv_bfloat16* asH = base;
        __nv_bfloat16* asL = base + SZ_A;
        __nv_bfloat16* bsH = base + 2 * SZ_A;
        __nv_bfloat16* bsL = base + 2 * SZ_A + SZ_B;
#pragma unroll
        for (int kk = 0; kk < BK; kk += 16) {
            wmma::fragment<wmma::matrix_a, 16, 16, 16, __nv_bfloat16, wmma::row_major> ah[4], al[4];
#pragma unroll
            for (int i = 0; i < 4; i++) {
                wmma::load_matrix_sync(ah[i], asH + (wm * 64 + i * 16) * LDA + kk, LDA);
                wmma::load_matrix_sync(al[i], asL + (wm * 64 + i * 16) * LDA + kk, LDA);
            }
#pragma unroll
            for (int j = 0; j < 4; j++) {
                wmma::fragment<wmma::matrix_b, 16, 16, 16, __nv_bfloat16, wmma::row_major> bh, bl;
                wmma::load_matrix_sync(bh, bsH + kk * LDB + wn * 64 + j * 16, LDB);
                wmma::load_matrix_sync(bl, bsL + kk * LDB + wn * 64 + j * 16, LDB);
#pragma unroll
                for (int i = 0; i < 4; i++) wmma::mma_sync(acc.a[i][j], ah[i], bh, acc.a[i][j]);
#pragma unroll
                for (int i = 0; i < 4; i++) wmma::mma_sync(acc.a[i][j], al[i], bh, acc.a[i][j]);
#pragma unroll
                for (int i = 0; i < 4; i++) wmma::mma_sync(acc.a[i][j], ah[i], bl, acc.a[i][j]);
            }
        }
    };

    load_tiles(0, 0);
    load_tiles(1, BK);
#pragma unroll 1
    for (int i = 0; i < NKIT; ++i) {
        asm volatile("cp.async.wait_group 1;\n" ::);
        __syncthreads();
        if (i + 2 < NKIT) load_tiles((i + 2) % 3, (i + 2) * BK);
        compute(i % 3);
    }
}

__global__ __launch_bounds__(128, 2) void xp_gemm() {
    extern __shared__ char smraw[];
    __nv_bfloat16* sm = reinterpret_cast<__nv_bfloat16*>(smraw);

    int m0 = blockIdx.x * BM;          // fast dim: m-tiles share B tile via L2
    int colTile = blockIdx.y;
    int t  = colTile >> 4;
    int p0 = (colTile & 15) * BN;

    int tid    = threadIdx.x;
    int warpId = tid >> 5;
    int wm = warpId & 1;
    int wn = warpId >> 1;

    AccXP acc;
    gemm_core_xp(g_WxH + (size_t)m0 * Kk, g_WxL + (size_t)m0 * Kk,
                 g_XtH + (size_t)t * Kk * Pp + p0, g_XtL + (size_t)t * Kk * Pp + p0,
                 sm, tid, wm, wn, acc);

    float* XPbase = g_XP + (size_t)t * Mm * Pp + (size_t)m0 * Pp + p0;
#pragma unroll
    for (int i = 0; i < 4; i++)
#pragma unroll
        for (int j = 0; j < 4; j++)
            wmma::store_matrix_sync(XPbase + (size_t)(wm * 64 + i * 16) * Pp + wn * 64 + j * 16,
                                    acc.a[i][j], Pp, wmma::mem_row_major);
}

// ==== persistent step kernel: 256x128 tiles, 8 warps (4x2), 64x64 warp tiles, 3-stage ====
struct AccST {
    wmma::fragment<wmma::accumulator, 16, 16, 16, float> a[4][4];
};

__global__ __launch_bounds__(256, 1) void lstm_persist() {
    extern __shared__ char smraw[];
    __nv_bfloat16* sm = reinterpret_cast<__nv_bfloat16*>(smraw);
    float* Zs = reinterpret_cast<float*>(smraw);                       // alias (135168 B used)
    float* bias_s = reinterpret_cast<float*>(smraw + 3 * BUF2 * 2);    // 256 floats, above Zs

    int p0 = (blockIdx.x & 15) * BN;          // 16 p-tiles
    int m0 = (blockIdx.x >> 4) * BM2;         // 8 m-tiles of 256
    int c0 = m0 >> 2;                          // 64 channels per tile

    int tid    = threadIdx.x;
    int warpId = tid >> 5;
    int wm = warpId & 3;      // 4 warps along M (64 rows each)
    int wn = warpId >> 2;     // 2 warps along N (64 cols each)

    const __nv_bfloat16* AH = g_WhH + (size_t)m0 * Kk;
    const __nv_bfloat16* AL = g_WhL + (size_t)m0 * Kk;

    // stage per-tile biases: bias_s[cl*4+g] for cl in 0..63
    if (tid < 256) {
        int cl = tid >> 2, g = tid & 3;
        bias_s[tid] = g_bias[g * Cc + c0 + cl];
    }

#pragma unroll 1
    for (int t = 0; t < Tt; ++t) {
        const __nv_bfloat16* BH = g_HH[t & 1] + p0;
        const __nv_bfloat16* BL = g_HL[t & 1] + p0;

        AccST acc;
        {
            const float* XPbase = g_XP + (size_t)t * Mm * Pp + (size_t)m0 * Pp + p0;
#pragma unroll
            for (int i = 0; i < 4; i++)
#pragma unroll
                for (int j = 0; j < 4; j++)
                    wmma::load_matrix_sync(acc.a[i][j],
                        XPbase + (size_t)(wm * 64 + i * 16) * Pp + wn * 64 + j * 16,
                        Pp, wmma::mem_row_major);
        }

        auto load_tiles = [&](int buf, int k0) {
            __nv_bfloat16* base = sm + buf * BUF2;
            __nv_bfloat16* asH = base;
            __nv_bfloat16* asL = base + SZ_A2;
            __nv_bfloat16* bsH = base + 2 * SZ_A2;
            __nv_bfloat16* bsL = base + 2 * SZ_A2 + SZ_B2;
#pragma unroll
            for (int it = 0; it < 4; ++it) {                 // A: 256 rows x 4 chunks
                int idx = tid + it * 256;
                int row = idx >> 2, q = idx & 3;
                cp16(asH + row * LDA + q * 8, AH + (size_t)row * Kk + k0 + q * 8);
                cp16(asL + row * LDA + q * 8, AL + (size_t)row * Kk + k0 + q * 8);
            }
#pragma unroll
            for (int it = 0; it < 2; ++it) {                 // B: 32 k-rows x 16 chunks
                int idx = tid + it * 256;
                int kk = idx >> 4, q = idx & 15;
                cp16(bsH + kk * LDB + q * 8, BH + (size_t)(k0 + kk) * Pp + q * 8);
                cp16(bsL + kk * LDB + q * 8, BL + (size_t)(k0 + kk) * Pp + q * 8);
            }
            CP_COMMIT();
        };

        auto compute = [&](int buf) {
            __nv_bfloat16* base = sm + buf * BUF2;
            __nv_bfloat16* asH = base;
            __nv_bfloat16* asL = base + SZ_A2;
            __nv_bfloat16* bsH = base + 2 * SZ_A2;
            __nv_bfloat16* bsL = base + 2 * SZ_A2 + SZ_B2;
#pragma unroll
            for (int kk = 0; kk < BK; kk += 16) {
                wmma::fragment<wmma::matrix_a, 16, 16, 16, __nv_bfloat16, wmma::row_major> ah[4], al[4];
#pragma unroll
                for (int i = 0; i < 4; i++) {
                    wmma::load_matrix_sync(ah[i], asH + (wm * 64 + i * 16) * LDA + kk, LDA);
                    wmma::load_matrix_sync(al[i], asL + (wm * 64 + i * 16) * LDA + kk, LDA);
                }
#pragma unroll
                for (int j = 0; j < 4; j++) {
                    wmma::fragment<wmma::matrix_b, 16, 16, 16, __nv_bfloat16, wmma::row_major> bh2, bl2;
                    wmma::load_matrix_sync(bh2, bsH + kk * LDB + wn * 64 + j * 16, LDB);
                    wmma::load_matrix_sync(bl2, bsL + kk * LDB + wn * 64 + j * 16, LDB);
#pragma unroll
                    for (int i = 0; i < 4; i++) wmma::mma_sync(acc.a[i][j], ah[i], bh2, acc.a[i][j]);
#pragma unroll
                    for (int i = 0; i < 4; i++) wmma::mma_sync(acc.a[i][j], al[i], bh2, acc.a[i][j]);
#pragma unroll
                    for (int i = 0; i < 4; i++) wmma::mma_sync(acc.a[i][j], ah[i], bl2, acc.a[i][j]);
                }
            }
        };

        load_tiles(0, 0);
        load_tiles(1, BK);
#pragma unroll 1
        for (int i = 0; i < NKIT; ++i) {
            asm volatile("cp.async.wait_group 1;\n" ::);
            __syncthreads();
            if (i + 2 < NKIT) load_tiles((i + 2) % 3, (i + 2) * BK);
            compute(i % 3);
        }

        __syncthreads();   // all reads of stage buffers done before Zs alias
#pragma unroll
        for (int i = 0; i < 4; i++)
#pragma unroll
            for (int j = 0; j < 4; j++)
                wmma::store_matrix_sync(Zs + (wm * 64 + i * 16) * LDZ + wn * 64 + j * 16,
                                        acc.a[i][j], LDZ, wmma::mem_row_major);
        __syncthreads();

        __nv_bfloat16* HoutH = g_HH[(t + 1) & 1];
        __nv_bfloat16* HoutL = g_HL[(t + 1) & 1];
#pragma unroll
        for (int it = 0; it < 32; it++) {
            int idx = tid + it * 256;     // 0..8191
            int cl = idx >> 7;            // 0..63
            int pl = idx & 127;
            int c = c0 + cl;
            int p = p0 + pl;

            float zi = Zs[(4 * cl + 0) * LDZ + pl] + bias_s[cl * 4 + 0];
            float zf = Zs[(4 * cl + 1) * LDZ + pl] + bias_s[cl * 4 + 1];
            float zo = Zs[(4 * cl + 2) * LDZ + pl] + bias_s[cl * 4 + 2];
            float zg = Zs[(4 * cl + 3) * LDZ + pl] + bias_s[cl * 4 + 3];

            float ig = 1.f / (1.f + __expf(-zi));
            float fg = 1.f / (1.f + __expf(-zf));
            float og = 1.f / (1.f + __expf(-zo));
            float gg = tanhf(zg);

            float cp = g_Cell[c * Pp + p];
            float cn = fg * cp + ig * gg;
            g_Cell[c * Pp + p] = cn;
            float h = og * tanhf(cn);

            __nv_bfloat16 hh, hl;
            bf16_split(h, hh, hl);
            HoutH[c * Pp + p] = hh;
            HoutL[c * Pp + p] = hl;

            g_Hseq[((size_t)t * Cc + c) * Pp + p] = h;
        }

        grid_barrier((unsigned)NBLK_ST * (t + 1));
    }
}

extern "C" void kernel_launch(void* const* d_in, const int* in_sizes, int n_in,
                              void* d_out, int out_size) {
    const float* x  = (const float*)d_in[0];
    const float* Wx = (const float*)d_in[1];
    const float* bx = (const float*)d_in[2];
    const float* Wh = (const float*)d_in[3];
    const float* bh = (const float*)d_in[4];
    float* out = (float*)d_out;

    cudaFuncSetAttribute(xp_gemm,      cudaFuncAttributeMaxDynamicSharedMemorySize, SMEM_XP);
    cudaFuncSetAttribute(lstm_persist, cudaFuncAttributeMaxDynamicSharedMemorySize, SMEM_ST);

    init_state<<<(Kk * Pp + 255) / 256, 256>>>();
    split_weights<<<(4 * Cc * Cc + 255) / 256, 256>>>(Wx, Wh, bx, bh);
    transpose_split_x<<<Bb * Cc * (Nn / 32), 256>>>(x);
    xp_gemm<<<dim3(16, 512), 128, SMEM_XP>>>();
    lstm_persist<<<NBLK_ST, 256, SMEM_ST>>>();
    transpose_out<<<Bb * Cc * (Nn / 32), 256>>>(out);
}

// round 15
// speedup vs baseline: 1.0344x; 1.0344x over previous
#include <cuda_runtime.h>
#include <cuda_bf16.h>
#include <mma.h>
#include <cstdint>

using namespace nvcuda;

#define Bb 8
#define Cc 512
#define Nn 256
#define Tt 32
#define Pp 2048   // B*N
#define Mm 2048   // 4*C
#define Kk 512    // C

#define BM 128
#define BN 128
#define BK 32
#define NKIT (Kk / BK)   // 16
#define LDA 40           // 32 + 8 pad (bf16)
#define LDB 136          // 128 + 8 pad
#define LDZ 132          // fp32 staging pitch

#define SZ_A (BM * LDA)              // 5120 bf16
#define SZ_B (BK * LDB)              // 4352 bf16
#define BUF_ELEMS (2 * SZ_A + 2 * SZ_B)   // 18944 bf16 per stage
#define SMEM_XP (3 * BUF_ELEMS * 2)       // 113664 B (3-stage)
#define SMEM_ST (2 * BUF_ELEMS * 2)       // 75776 B (2-stage)

#define NBLK_ST 256      // persistent step grid (16 m-tiles x 16 p-tiles); <= 296 resident

// ------------ device scratch (no allocs allowed) ------------
__device__ __align__(16) __nv_bfloat16 g_XtH[(size_t)Tt * Kk * Pp]; // [t][k][p]
__device__ __align__(16) __nv_bfloat16 g_XtL[(size_t)Tt * Kk * Pp];
__device__ __align__(16) float         g_XP[(size_t)Tt * Mm * Pp];  // [t][m][p], m=4c+g
__device__ __align__(16) float         g_Hseq[(size_t)Tt * Cc * Pp];// [t][c][p]
__device__ __align__(16) __nv_bfloat16 g_WxH[Mm * Kk], g_WxL[Mm * Kk]; // rows m=4c+g
__device__ __align__(16) __nv_bfloat16 g_WhH[Mm * Kk], g_WhL[Mm * Kk];
__device__ __align__(16) __nv_bfloat16 g_HH[2][Kk * Pp], g_HL[2][Kk * Pp]; // H: [k][p]
__device__ __align__(16) float         g_Cell[Cc * Pp];
__device__ unsigned g_colcnt[16];    // per-p-column step counters

// ------------ cp.async helpers ------------
__device__ __forceinline__ void cp16(void* dst, const void* src) {
    unsigned int d = (unsigned int)__cvta_generic_to_shared(dst);
    asm volatile("cp.async.cg.shared.global [%0], [%1], 16;\n" :: "r"(d), "l"(src));
}
#define CP_COMMIT() asm volatile("cp.async.commit_group;\n" ::)
#define CP_WAIT1()  asm volatile("cp.async.wait_group 1;\n" ::)
#define CP_WAIT0()  asm volatile("cp.async.wait_group 0;\n" ::)

__device__ __forceinline__ void bf16_split(float v, __nv_bfloat16& h, __nv_bfloat16& l) {
    h = __float2bfloat16(v);
    l = __float2bfloat16(v - __bfloat162float(h));
}

// ------------ setup kernels ------------
__global__ void init_state() {
    int i = blockIdx.x * blockDim.x + threadIdx.x;
    if (i < 16) g_colcnt[i] = 0;               // reset each graph replay
    if (i < Kk * Pp) {
        __nv_bfloat16 z = __float2bfloat16(0.f);
        g_HH[0][i] = z; g_HH[1][i] = z;
        g_HL[0][i] = z; g_HL[1][i] = z;
        g_Cell[i] = 0.f;
    }
}

__global__ void split_weights(const float* __restrict__ Wx, const float* __restrict__ Wh) {
    int idx = blockIdx.x * blockDim.x + threadIdx.x;
    if (idx >= 4 * Cc * Cc) return;
    int g = idx >> 18;
    int rem = idx & ((1 << 18) - 1);
    int c = rem >> 9;
    int k = rem & 511;
    int m = (c << 2) | g;
    __nv_bfloat16 h, l;
    bf16_split(Wx[idx], h, l);
    g_WxH[m * Kk + k] = h; g_WxL[m * Kk + k] = l;
    bf16_split(Wh[idx], h, l);
    g_WhH[m * Kk + k] = h; g_WhL[m * Kk + k] = l;
}

// x (B,C,N,T) -> Xt hi/lo [t][c][b*N+n]
__global__ void transpose_split_x(const float* __restrict__ x) {
    __shared__ float tile[32][33];
    int bid   = blockIdx.x;
    int ntile = bid & 7;
    int bc    = bid >> 3;
    int c     = bc & (Cc - 1);
    int b     = bc >> 9;
    int tid = threadIdx.x;
    int tr = tid >> 5, tc = tid & 31;
    const float* src = x + ((size_t)(b * Cc + c) * Nn + ntile * 32) * Tt;
#pragma unroll
    for (int r0 = 0; r0 < 32; r0 += 8)
        tile[r0 + tr][tc] = src[(size_t)(r0 + tr) * Tt + tc];
    __syncthreads();
#pragma unroll
    for (int r0 = 0; r0 < 32; r0 += 8) {
        int t = r0 + tr;
        float v = tile[tc][t];
        __nv_bfloat16 h, l;
        bf16_split(v, h, l);
        size_t o = ((size_t)t * Kk + c) * Pp + b * Nn + ntile * 32 + tc;
        g_XtH[o] = h; g_XtL[o] = l;
    }
}

// g_Hseq[t][c][b*N+n] -> out (B,C,N,T)
__global__ void transpose_out(float* __restrict__ out) {
    __shared__ float tile[32][33];
    int bid   = blockIdx.x;
    int ntile = bid & 7;
    int bc    = bid >> 3;
    int c     = bc & (Cc - 1);
    int b     = bc >> 9;
    int tid = threadIdx.x;
    int tr = tid >> 5, tc = tid & 31;
#pragma unroll
    for (int r0 = 0; r0 < 32; r0 += 8) {
        int t = r0 + tr;
        tile[tc][t] = g_Hseq[((size_t)t * Cc + c) * Pp + b * Nn + ntile * 32 + tc];
    }
    __syncthreads();
    float* dst = out + ((size_t)(b * Cc + c) * Nn + ntile * 32) * Tt;
#pragma unroll
    for (int r0 = 0; r0 < 32; r0 += 8) {
        int n = r0 + tr;
        dst[(size_t)n * Tt + tc] = tile[n][tc];
    }
}

// =========== CORE A: 128 thr, 2x2 warps, 64x64 tiles, 3-stage (for xp_gemm) ===========
struct AccXP {
    wmma::fragment<wmma::accumulator, 16, 16, 16, float> a[4][4];
};

__device__ __forceinline__ void gemm_core_xp(
    const __nv_bfloat16* __restrict__ AH, const __nv_bfloat16* __restrict__ AL,
    const __nv_bfloat16* __restrict__ BH, const __nv_bfloat16* __restrict__ BL,
    __nv_bfloat16* sm, int tid, int wm, int wn, AccXP& acc)
{
#pragma unroll
    for (int i = 0; i < 4; i++)
#pragma unroll
        for (int j = 0; j < 4; j++) wmma::fill_fragment(acc.a[i][j], 0.f);

    auto load_tiles = [&](int buf, int k0) {
        __nv_bfloat16* base = sm + buf * BUF_ELEMS;
        __nv_bfloat16* asH = base;
        __nv_bfloat16* asL = base + SZ_A;
        __nv_bfloat16* bsH = base + 2 * SZ_A;
        __nv_bfloat16* bsL = base + 2 * SZ_A + SZ_B;
#pragma unroll
        for (int it = 0; it < 4; ++it) {
            int idx = tid + it * 128;
            int row = idx >> 2, q = idx & 3;
            cp16(asH + row * LDA + q * 8, AH + (size_t)row * Kk + k0 + q * 8);
            cp16(asL + row * LDA + q * 8, AL + (size_t)row * Kk + k0 + q * 8);
        }
#pragma unroll
        for (int it = 0; it < 4; ++it) {
            int idx = tid + it * 128;
            int kk = idx >> 4, q = idx & 15;
            cp16(bsH + kk * LDB + q * 8, BH + (size_t)(k0 + kk) * Pp + q * 8);
            cp16(bsL + kk * LDB + q * 8, BL + (size_t)(k0 + kk) * Pp + q * 8);
        }
        CP_COMMIT();
    };

    auto compute = [&](int buf) {
        __nv_bfloat16* base = sm + buf * BUF_ELEMS;
        __nv_bfloat16* asH = base;
        __nv_bfloat16* asL = base + SZ_A;
        __nv_bfloat16* bsH = base + 2 * SZ_A;
        __nv_bfloat16* bsL = base + 2 * SZ_A + SZ_B;
#pragma unroll
        for (int kk = 0; kk < BK; kk += 16) {
            wmma::fragment<wmma::matrix_a, 16, 16, 16, __nv_bfloat16, wmma::row_major> ah[4], al[4];
#pragma unroll
            for (int i = 0; i < 4; i++) {
                wmma::load_matrix_sync(ah[i], asH + (wm * 64 + i * 16) * LDA + kk, LDA);
                wmma::load_matrix_sync(al[i], asL + (wm * 64 + i * 16) * LDA + kk, LDA);
            }
#pragma unroll
            for (int j = 0; j < 4; j++) {
                wmma::fragment<wmma::matrix_b, 16, 16, 16, __nv_bfloat16, wmma::row_major> bh, bl;
                wmma::load_matrix_sync(bh, bsH + kk * LDB + wn * 64 + j * 16, LDB);
                wmma::load_matrix_sync(bl, bsL + kk * LDB + wn * 64 + j * 16, LDB);
#pragma unroll
                for (int i = 0; i < 4; i++) wmma::mma_sync(acc.a[i][j], ah[i], bh, acc.a[i][j]);
#pragma unroll
                for (int i = 0; i < 4; i++) wmma::mma_sync(acc.a[i][j], al[i], bh, acc.a[i][j]);
#pragma unroll
                for (int i = 0; i < 4; i++) wmma::mma_sync(acc.a[i][j], ah[i], bl, acc.a[i][j]);
            }
        }
    };

    load_tiles(0, 0);
    load_tiles(1, BK);
#pragma unroll 1
    for (int i = 0; i < NKIT; ++i) {
        asm volatile("cp.async.wait_group 1;\n" ::);
        __syncthreads();
        if (i + 2 < NKIT) load_tiles((i + 2) % 3, (i + 2) * BK);
        compute(i % 3);
    }
}

__global__ __launch_bounds__(128, 2) void xp_gemm() {
    extern __shared__ char smraw[];
    __nv_bfloat16* sm = reinterpret_cast<__nv_bfloat16*>(smraw);

    int m0 = blockIdx.x * BM;          // fast dim: m-tiles share B tile via L2
    int colTile = blockIdx.y;
    int t  = colTile >> 4;
    int p0 = (colTile & 15) * BN;

    int tid    = threadIdx.x;
    int warpId = tid >> 5;
    int wm = warpId & 1;
    int wn = warpId >> 1;

    AccXP acc;
    gemm_core_xp(g_WxH + (size_t)m0 * Kk, g_WxL + (size_t)m0 * Kk,
                 g_XtH + (size_t)t * Kk * Pp + p0, g_XtL + (size_t)t * Kk * Pp + p0,
                 sm, tid, wm, wn, acc);

    float* XPbase = g_XP + (size_t)t * Mm * Pp + (size_t)m0 * Pp + p0;
#pragma unroll
    for (int i = 0; i < 4; i++)
#pragma unroll
        for (int j = 0; j < 4; j++)
            wmma::store_matrix_sync(XPbase + (size_t)(wm * 64 + i * 16) * Pp + wn * 64 + j * 16,
                                    acc.a[i][j], Pp, wmma::mem_row_major);
}

// ===== persistent step kernel: core B, 32 steps, PER-COLUMN sync =====
struct AccST {
    wmma::fragment<wmma::accumulator, 16, 16, 16, float> a[2][4];
};

__global__ __launch_bounds__(256, 2) void lstm_persist(const float* __restrict__ bx,
                                                       const float* __restrict__ bh) {
    extern __shared__ char smraw[];
    __nv_bfloat16* sm = reinterpret_cast<__nv_bfloat16*>(smraw);
    float* Zs = reinterpret_cast<float*>(smraw);   // alias, used after final GEMM sync

    int pcol = blockIdx.x & 15;
    int p0 = pcol * BN;
    int m0 = (blockIdx.x >> 4) * BM;

    int tid    = threadIdx.x;
    int warpId = tid >> 5;
    int wm = warpId & 3;
    int wn = warpId >> 2;

    const __nv_bfloat16* AH = g_WhH + (size_t)m0 * Kk;
    const __nv_bfloat16* AL = g_WhL + (size_t)m0 * Kk;

    // per-thread epilogue biases (c fixed per (tid,it) across steps)
    float biasv[16][4];
#pragma unroll
    for (int it = 0; it < 16; it++) {
        int idx = tid + it * 256;
        int cl = idx >> 7;
        int c = (m0 >> 2) + cl;
        biasv[it][0] = bx[c] + bh[c];
        biasv[it][1] = bx[Cc + c] + bh[Cc + c];
        biasv[it][2] = bx[2 * Cc + c] + bh[2 * Cc + c];
        biasv[it][3] = bx[3 * Cc + c] + bh[3 * Cc + c];
    }

#pragma unroll 1
    for (int t = 0; t < Tt; ++t) {
        // XP accumulator load: step-independent — issue BEFORE the column wait
        AccST acc;
        {
            const float* XPbase = g_XP + (size_t)t * Mm * Pp + (size_t)m0 * Pp + p0;
#pragma unroll
            for (int i = 0; i < 2; i++)
#pragma unroll
                for (int j = 0; j < 4; j++)
                    wmma::load_matrix_sync(acc.a[i][j],
                        XPbase + (size_t)(wm * 32 + i * 16) * Pp + wn * 64 + j * 16,
                        Pp, wmma::mem_row_major);
        }

        // column sync: H[t&1] for this p-column fully written by the 16 m-CTAs
        if (t > 0) {
            if (tid == 0) {
                volatile unsigned* p = &g_colcnt[pcol];
                unsigned target = 16u * (unsigned)t;
                while (*p < target) { }
                __threadfence();
            }
            __syncthreads();
        }

        const __nv_bfloat16* BH = g_HH[t & 1] + p0;
        const __nv_bfloat16* BL = g_HL[t & 1] + p0;

        auto load_tiles = [&](int buf, int k0) {
            __nv_bfloat16* base = sm + buf * BUF_ELEMS;
            __nv_bfloat16* asH = base;
            __nv_bfloat16* asL = base + SZ_A;
            __nv_bfloat16* bsH = base + 2 * SZ_A;
            __nv_bfloat16* bsL = base + 2 * SZ_A + SZ_B;
#pragma unroll
            for (int it = 0; it < 2; ++it) {
                int idx = tid + it * 256;
                int row = idx >> 2, q = idx & 3;
                cp16(asH + row * LDA + q * 8, AH + (size_t)row * Kk + k0 + q * 8);
                cp16(asL + row * LDA + q * 8, AL + (size_t)row * Kk + k0 + q * 8);
            }
#pragma unroll
            for (int it = 0; it < 2; ++it) {
                int idx = tid + it * 256;
                int kk = idx >> 4, q = idx & 15;
                cp16(bsH + kk * LDB + q * 8, BH + (size_t)(k0 + kk) * Pp + q * 8);
                cp16(bsL + kk * LDB + q * 8, BL + (size_t)(k0 + kk) * Pp + q * 8);
            }
            CP_COMMIT();
        };

        auto compute = [&](int buf) {
            __nv_bfloat16* base = sm + buf * BUF_ELEMS;
            __nv_bfloat16* asH = base;
            __nv_bfloat16* asL = base + SZ_A;
            __nv_bfloat16* bsH = base + 2 * SZ_A;
            __nv_bfloat16* bsL = base + 2 * SZ_A + SZ_B;
#pragma unroll
            for (int kk = 0; kk < BK; kk += 16) {
                wmma::fragment<wmma::matrix_a, 16, 16, 16, __nv_bfloat16, wmma::row_major> ah[2], al[2];
#pragma unroll
                for (int i = 0; i < 2; i++) {
                    wmma::load_matrix_sync(ah[i], asH + (wm * 32 + i * 16) * LDA + kk, LDA);
                    wmma::load_matrix_sync(al[i], asL + (wm * 32 + i * 16) * LDA + kk, LDA);
                }
#pragma unroll
                for (int j = 0; j < 4; j++) {
                    wmma::fragment<wmma::matrix_b, 16, 16, 16, __nv_bfloat16, wmma::row_major> bh2, bl2;
                    wmma::load_matrix_sync(bh2, bsH + kk * LDB + wn * 64 + j * 16, LDB);
                    wmma::load_matrix_sync(bl2, bsL + kk * LDB + wn * 64 + j * 16, LDB);
#pragma unroll
                    for (int i = 0; i < 2; i++) {
                        wmma::mma_sync(acc.a[i][j], ah[i], bh2, acc.a[i][j]);
                        wmma::mma_sync(acc.a[i][j], al[i], bh2, acc.a[i][j]);
                        wmma::mma_sync(acc.a[i][j], ah[i], bl2, acc.a[i][j]);
                    }
                }
            }
        };

        load_tiles(0, 0);
#pragma unroll 1
        for (int i = 0; i < NKIT; ++i) {
            if (i + 1 < NKIT) { load_tiles((i + 1) & 1, (i + 1) * BK); CP_WAIT1(); }
            else              { CP_WAIT0(); }
            __syncthreads();
            compute(i & 1);
            __syncthreads();
        }

#pragma unroll
        for (int i = 0; i < 2; i++)
#pragma unroll
            for (int j = 0; j < 4; j++)
                wmma::store_matrix_sync(Zs + (wm * 32 + i * 16) * LDZ + wn * 64 + j * 16,
                                        acc.a[i][j], LDZ, wmma::mem_row_major);
        __syncthreads();

        __nv_bfloat16* HoutH = g_HH[(t + 1) & 1];
        __nv_bfloat16* HoutL = g_HL[(t + 1) & 1];
#pragma unroll
        for (int it = 0; it < 16; it++) {
            int idx = tid + it * 256;
            int cl = idx >> 7;
            int pl = idx & 127;
            int c = (m0 >> 2) + cl;
            int p = p0 + pl;

            float zi = Zs[(4 * cl + 0) * LDZ + pl] + biasv[it][0];
            float zf = Zs[(4 * cl + 1) * LDZ + pl] + biasv[it][1];
            float zo = Zs[(4 * cl + 2) * LDZ + pl] + biasv[it][2];
            float zg = Zs[(4 * cl + 3) * LDZ + pl] + biasv[it][3];

            float ig = 1.f / (1.f + __expf(-zi));
            float fg = 1.f / (1.f + __expf(-zf));
            float og = 1.f / (1.f + __expf(-zo));
            float gg = tanhf(zg);

            float cp = g_Cell[c * Pp + p];
            float cn = fg * cp + ig * gg;
            g_Cell[c * Pp + p] = cn;
            float h = og * tanhf(cn);

            __nv_bfloat16 hh, hl;
            bf16_split(h, hh, hl);
            HoutH[c * Pp + p] = hh;
            HoutL[c * Pp + p] = hl;

            g_Hseq[((size_t)t * Cc + c) * Pp + p] = h;
        }

        // column arrive: publish H writes, bump this column's counter
        __threadfence();
        __syncthreads();
        if (tid == 0) atomicAdd(&g_colcnt[pcol], 1u);
    }
}

extern "C" void kernel_launch(void* const* d_in, const int* in_sizes, int n_in,
                              void* d_out, int out_size) {
    const float* x  = (const float*)d_in[0];
    const float* Wx = (const float*)d_in[1];
    const float* bx = (const float*)d_in[2];
    const float* Wh = (const float*)d_in[3];
    const float* bh = (const float*)d_in[4];
    float* out = (float*)d_out;

    cudaFuncSetAttribute(xp_gemm,      cudaFuncAttributeMaxDynamicSharedMemorySize, SMEM_XP);
    cudaFuncSetAttribute(lstm_persist, cudaFuncAttributeMaxDynamicSharedMemorySize, SMEM_ST);

    init_state<<<(Kk * Pp + 255) / 256, 256>>>();
    split_weights<<<(4 * Cc * Cc + 255) / 256, 256>>>(Wx, Wh);
    transpose_split_x<<<Bb * Cc * (Nn / 32), 256>>>(x);
    xp_gemm<<<dim3(16, 512), 128, SMEM_XP>>>();
    lstm_persist<<<NBLK_ST, 256, SMEM_ST>>>(bx, bh);
    transpose_out<<<Bb * Cc * (Nn / 32), 256>>>(out);
}